// round 3
// baseline (speedup 1.0000x reference)
#include <cuda_runtime.h>

#define Bx 2
#define Nx 32
#define Cx 128
#define Px 8192
#define G3x 8
#define NEGV (-1e30f)

// Scratch: transposed features [b][p][c]  (8 MB, static device global — allowed)
__device__ float g_featT[(size_t)Bx * Px * Cx];

// ---------------------------------------------------------------------------
// K0: transpose point_features [B][C][P] -> g_featT [B][P][C]
// 32x32 tiles via shared memory, +1 pad to kill bank conflicts.
// ---------------------------------------------------------------------------
__global__ void __launch_bounds__(256) roipool_transpose_kernel(
    const float* __restrict__ feat)
{
    __shared__ float tile[32][33];
    const int b  = blockIdx.z;
    const int c0 = blockIdx.y * 32;
    const int p0 = blockIdx.x * 32;
    const int tx = threadIdx.x;      // 0..31
    const int ty = threadIdx.y;      // 0..7

    const float* src = feat + (size_t)b * Cx * Px;
#pragma unroll
    for (int i = 0; i < 32; i += 8)
        tile[ty + i][tx] = src[(size_t)(c0 + ty + i) * Px + (p0 + tx)];
    __syncthreads();

    float* dst = g_featT + (size_t)b * Px * Cx;
#pragma unroll
    for (int i = 0; i < 32; i += 8)
        dst[(size_t)(p0 + ty + i) * Cx + (c0 + tx)] = tile[tx][ty + i];
}

// ---------------------------------------------------------------------------
// K1: one CTA per (b, n) box.
//  Phase A: ordered compaction of inside & valid point indices into smem.
//  Phase B: per-channel, per-bin max over featT (coalesced lanes = channels).
// ---------------------------------------------------------------------------
__global__ void __launch_bounds__(256) roipool_main_kernel(
    const float* __restrict__ boxes,    // [B][N][6]
    const int*   __restrict__ offset,   // [B]
    const float* __restrict__ pc,       // [B][P][3]
    float*       __restrict__ out)      // [B][N][C][8]
{
    __shared__ int   s_idx[Px];         // 32 KB: compacted point indices (ordered)
    __shared__ int   s_warp[8];
    __shared__ int   s_base;
    __shared__ float s_box[6];

    const int bn   = blockIdx.x;
    const int b    = bn / Nx;
    const int t    = threadIdx.x;
    const int lane = t & 31;
    const int wid  = t >> 5;

    if (t < 6)  s_box[t] = boxes[bn * 6 + t];
    if (t == 0) s_base = 0;
    __syncthreads();

    const float cx = s_box[0], cy = s_box[1], cz = s_box[2];
    const float hx = s_box[3] * 0.5f, hy = s_box[4] * 0.5f, hz = s_box[5] * 0.5f;
    const float lox = cx - hx, hix = cx + hx;
    const float loy = cy - hy, hiy = cy + hy;
    const float loz = cz - hz, hiz = cz + hz;

    const int off = offset[b];
    const float* pcb = pc + (size_t)b * Px * 3;

    // ---- Phase A: ordered stream compaction -------------------------------
    for (int base = 0; base < Px; base += 256) {
        const int p = base + t;
        bool flag = false;
        if (p < off) {
            const float x = pcb[p * 3 + 0];
            const float y = pcb[p * 3 + 1];
            const float z = pcb[p * 3 + 2];
            flag = (x >= lox) & (x <= hix) &
                   (y >= loy) & (y <= hiy) &
                   (z >= loz) & (z <= hiz);
        }
        const unsigned bal = __ballot_sync(0xffffffffu, flag);
        const int pos = __popc(bal & ((1u << lane) - 1u));
        if (lane == 0) s_warp[wid] = __popc(bal);
        __syncthreads();

        int wbase = 0;
#pragma unroll
        for (int w = 0; w < 8; w++)
            if (w < wid) wbase += s_warp[w];
        int ctot = 0;
#pragma unroll
        for (int w = 0; w < 8; w++) ctot += s_warp[w];

        if (flag) s_idx[s_base + wbase + pos] = p;
        __syncthreads();
        if (t == 0) s_base += ctot;
        __syncthreads();
    }
    const int cnt = s_base;

    // ---- Phase B: per-(channel, bin) max -----------------------------------
    // thread t -> channel c = t & 127, bins [kbase, kbase+4)
    const int c     = t & 127;
    const int kbase = (t >> 7) * 4;
    float* ob = out + ((size_t)bn * Cx + c) * G3x;

    if (cnt == 0) {
#pragma unroll
        for (int kk = 0; kk < 4; kk++) ob[kbase + kk] = 0.0f;
        return;
    }

    const float* ft = g_featT + (size_t)b * Px * Cx + c;
#pragma unroll
    for (int kk = 0; kk < 4; kk++) {
        const int k  = kbase + kk;
        const int st = (k * cnt) >> 3;                 // floor(k*cnt/8)
        const int en = ((k + 1) * cnt + 7) >> 3;       // ceil((k+1)*cnt/8)
        float m = NEGV;
#pragma unroll 4
        for (int j = st; j < en; j++) {
            const int p = s_idx[j];
            m = fmaxf(m, __ldg(ft + (size_t)p * Cx));
        }
        ob[k] = m;
    }
}

// ---------------------------------------------------------------------------
// Harness entry
// ---------------------------------------------------------------------------
extern "C" void kernel_launch(void* const* d_in, const int* in_sizes, int n_in,
                              void* d_out, int out_size)
{
    const float* boxes  = (const float*)d_in[0];   // (B, N, 6)
    const float* feat   = (const float*)d_in[1];   // (B, C, P)
    const int*   offset = (const int*)  d_in[2];   // (B,)
    const float* pc     = (const float*)d_in[3];   // (B, P, 3)
    float*       out    = (float*)d_out;           // (B, N, C, 2, 2, 2)

    dim3 tb(32, 8);
    dim3 tg(Px / 32, Cx / 32, Bx);
    roipool_transpose_kernel<<<tg, tb>>>(feat);
    roipool_main_kernel<<<Bx * Nx, 256>>>(boxes, offset, pc, out);
}

// round 4
// speedup vs baseline: 1.7734x; 1.7734x over previous
#include <cuda_runtime.h>

#define Bx 2
#define Nx 32
#define Cx 128
#define Px 8192
#define NB (Bx * Nx)
#define G3x 8
#define NEGV (-1e30f)

// Scratch (static device globals — allowed)
__device__ float g_featT[(size_t)Bx * Px * Cx];   // transposed features [b][p][c]
__device__ int   g_idx[NB * Px];                  // compacted inside-point indices per box
__device__ int   g_cnt[NB];                       // inside count per box

#define TP_BLOCKS (Bx * (Cx / 32) * (Px / 32))    // 2048 transpose tiles

// ---------------------------------------------------------------------------
// Kernel A (fused): blocks [0,TP_BLOCKS) transpose feat -> g_featT;
//                   blocks [TP_BLOCKS, TP_BLOCKS+NB) compact inside points.
// ---------------------------------------------------------------------------
__global__ void __launch_bounds__(256) roipool_prep_kernel(
    const float* __restrict__ feat,    // [B][C][P]
    const float* __restrict__ boxes,   // [B][N][6]
    const int*   __restrict__ offset,  // [B]
    const float* __restrict__ pc)      // [B][P][3]
{
    __shared__ float tile[32][33];
    const int t = threadIdx.x;

    if (blockIdx.x < TP_BLOCKS) {
        // ---- transpose 32x32 tile ----
        int id = blockIdx.x;
        const int p0 = (id & 255) * 32; id >>= 8;
        const int c0 = (id & 3) * 32;   id >>= 2;
        const int b  = id;
        const int tx = t & 31, ty = t >> 5;
        const float* src = feat + (size_t)b * Cx * Px;
#pragma unroll
        for (int i = 0; i < 32; i += 8)
            tile[ty + i][tx] = src[(size_t)(c0 + ty + i) * Px + (p0 + tx)];
        __syncthreads();
        float* dst = g_featT + (size_t)b * Px * Cx;
#pragma unroll
        for (int i = 0; i < 32; i += 8)
            dst[(size_t)(p0 + ty + i) * Cx + (c0 + tx)] = tile[tx][ty + i];
        return;
    }

    // ---- compact: ordered stream compaction, flags kept in registers ----
    __shared__ int   s_wcnt[8];
    __shared__ float s_box[6];
    const int bn   = blockIdx.x - TP_BLOCKS;
    const int b    = bn / Nx;
    const int lane = t & 31;
    const int w    = t >> 5;

    if (t < 6) s_box[t] = boxes[bn * 6 + t];
    __syncthreads();

    const float hx = s_box[3] * 0.5f, hy = s_box[4] * 0.5f, hz = s_box[5] * 0.5f;
    const float lox = s_box[0] - hx, hix = s_box[0] + hx;
    const float loy = s_box[1] - hy, hiy = s_box[1] + hy;
    const float loz = s_box[2] - hz, hiz = s_box[2] + hz;

    const int off = offset[b];
    const float* pcb = pc + (size_t)b * Px * 3;
    const int pbase = w * 1024;             // warp w owns points [w*1024, w*1024+1024)

    unsigned myflags = 0;                   // bit i = my flag in iteration i
    unsigned mybal   = 0;                   // lane i holds iteration-i ballot
    int cntw = 0;
#pragma unroll 8
    for (int i = 0; i < 32; i++) {
        const int p = pbase + i * 32 + lane;
        bool flag = false;
        if (p < off) {
            const float x = pcb[p * 3 + 0];
            const float y = pcb[p * 3 + 1];
            const float z = pcb[p * 3 + 2];
            flag = (x >= lox) & (x <= hix) &
                   (y >= loy) & (y <= hiy) &
                   (z >= loz) & (z <= hiz);
        }
        const unsigned bal = __ballot_sync(0xffffffffu, flag);
        myflags |= ((unsigned)flag) << i;
        if (lane == i) mybal = bal;
        cntw += __popc(bal);
    }
    if (lane == 0) s_wcnt[w] = cntw;
    __syncthreads();

    int base = 0, tot = 0;
#pragma unroll
    for (int ww = 0; ww < 8; ww++) {
        if (ww < w) base += s_wcnt[ww];
        tot += s_wcnt[ww];
    }

    int* gi = g_idx + bn * Px;
#pragma unroll 8
    for (int i = 0; i < 32; i++) {
        const unsigned bal = __shfl_sync(0xffffffffu, mybal, i);
        if ((myflags >> i) & 1u)
            gi[base + __popc(bal & ((1u << lane) - 1u))] = pbase + i * 32 + lane;
        base += __popc(bal);
    }
    if (t == 0) g_cnt[bn] = tot;
}

// ---------------------------------------------------------------------------
// Kernel B: one CTA per (box, bin). Thread = channel. Index list staged to
// smem, then independent coalesced gathers with 4 running maxes (MLP=4).
// ---------------------------------------------------------------------------
__global__ void __launch_bounds__(128) roipool_max_kernel(
    float* __restrict__ out)               // [B][N][C][8]
{
    __shared__ int s_pidx[1032];            // max bin size = ceil(8192/8)+1 = 1025
    const int k  = blockIdx.x & 7;
    const int bn = blockIdx.x >> 3;
    const int b  = bn / Nx;
    const int c  = threadIdx.x;

    const int cnt = g_cnt[bn];
    float* ob = out + ((size_t)bn * Cx + c) * G3x + k;
    if (cnt == 0) { *ob = 0.0f; return; }

    const int st = (k * cnt) >> 3;                 // floor(k*cnt/8)
    const int en = ((k + 1) * cnt + 7) >> 3;       // ceil((k+1)*cnt/8)
    const int nb = en - st;

    const int* gi = g_idx + bn * Px + st;
    for (int j = c; j < nb; j += 128) s_pidx[j] = gi[j];
    __syncthreads();

    const float* ft = g_featT + (size_t)b * Px * Cx + c;
    float m0 = NEGV, m1 = NEGV, m2 = NEGV, m3 = NEGV;
    int j = 0;
    for (; j + 3 < nb; j += 4) {
        const int p0 = s_pidx[j + 0];
        const int p1 = s_pidx[j + 1];
        const int p2 = s_pidx[j + 2];
        const int p3 = s_pidx[j + 3];
        m0 = fmaxf(m0, ft[(size_t)p0 * Cx]);
        m1 = fmaxf(m1, ft[(size_t)p1 * Cx]);
        m2 = fmaxf(m2, ft[(size_t)p2 * Cx]);
        m3 = fmaxf(m3, ft[(size_t)p3 * Cx]);
    }
    for (; j < nb; j++) m0 = fmaxf(m0, ft[(size_t)s_pidx[j] * Cx]);
    *ob = fmaxf(fmaxf(m0, m1), fmaxf(m2, m3));
}

// ---------------------------------------------------------------------------
// Harness entry
// ---------------------------------------------------------------------------
extern "C" void kernel_launch(void* const* d_in, const int* in_sizes, int n_in,
                              void* d_out, int out_size)
{
    const float* boxes  = (const float*)d_in[0];   // (B, N, 6)
    const float* feat   = (const float*)d_in[1];   // (B, C, P)
    const int*   offset = (const int*)  d_in[2];   // (B,)
    const float* pc     = (const float*)d_in[3];   // (B, P, 3)
    float*       out    = (float*)d_out;           // (B, N, C, 2, 2, 2)

    roipool_prep_kernel<<<TP_BLOCKS + NB, 256>>>(feat, boxes, offset, pc);
    roipool_max_kernel<<<NB * G3x, 128>>>(out);
}

// round 5
// speedup vs baseline: 1.9981x; 1.1267x over previous
#include <cuda_runtime.h>

#define Bx 2
#define Nx 32
#define Cx 128
#define Px 8192
#define NB (Bx * Nx)
#define G3x 8
#define NEGV (-1e30f)

// Scratch (static device globals — allowed)
__device__ float g_featT[(size_t)Bx * Px * Cx];   // transposed features [b][p][c]
__device__ int   g_idx[NB * Px];                  // compacted inside-point indices per box
__device__ int   g_cnt[NB];                       // inside count per box

#define TP_BLOCKS (Bx * (Cx / 32) * (Px / 32))    // 2048 transpose tiles

// ---------------------------------------------------------------------------
// Kernel A (fused): blocks [0,NB) compact inside points;
//                   blocks [NB, NB+TP_BLOCKS) transpose feat -> g_featT.
// Transpose is float4 on both the load and store side.
// ---------------------------------------------------------------------------
__global__ void __launch_bounds__(256) roipool_prep_kernel(
    const float* __restrict__ feat,    // [B][C][P]
    const float* __restrict__ boxes,   // [B][N][6]
    const int*   __restrict__ offset,  // [B]
    const float* __restrict__ pc)      // [B][P][3]
{
    const int t = threadIdx.x;

    if (blockIdx.x >= NB) {
        // ---- transpose 32(C) x 32(P) tile, vectorized ----
        __shared__ float tile[32][33];           // [c][p]
        int id = blockIdx.x - NB;
        const int p0 = (id & 255) * 32; id >>= 8;
        const int c0 = (id & 3) * 32;   id >>= 2;
        const int b  = id;

        // load: tx = 0..7 (float4 along P), ty = 0..31 (channel)
        {
            const int tx = t & 7, ty = t >> 3;
            const float4 v = *(const float4*)(feat + (size_t)b * Cx * Px
                                              + (size_t)(c0 + ty) * Px + p0 + tx * 4);
            tile[ty][tx * 4 + 0] = v.x;
            tile[ty][tx * 4 + 1] = v.y;
            tile[ty][tx * 4 + 2] = v.z;
            tile[ty][tx * 4 + 3] = v.w;
        }
        __syncthreads();
        // store: cx = 0..7 (float4 along C), py = 0..31 (point)
        {
            const int cx = t & 7, py = t >> 3;
            float4 o;
            o.x = tile[cx * 4 + 0][py];
            o.y = tile[cx * 4 + 1][py];
            o.z = tile[cx * 4 + 2][py];
            o.w = tile[cx * 4 + 3][py];
            *(float4*)(g_featT + (size_t)b * Px * Cx
                       + (size_t)(p0 + py) * Cx + c0 + cx * 4) = o;
        }
        return;
    }

    // ---- compaction: ordered, flags kept in registers, 2 barriers total ----
    __shared__ int   s_wcnt[8];
    __shared__ float s_box[6];
    const int bn   = blockIdx.x;
    const int b    = bn / Nx;
    const int lane = t & 31;
    const int w    = t >> 5;

    if (t < 6) s_box[t] = boxes[bn * 6 + t];
    __syncthreads();

    const float hx = s_box[3] * 0.5f, hy = s_box[4] * 0.5f, hz = s_box[5] * 0.5f;
    const float lox = s_box[0] - hx, hix = s_box[0] + hx;
    const float loy = s_box[1] - hy, hiy = s_box[1] + hy;
    const float loz = s_box[2] - hz, hiz = s_box[2] + hz;

    const int off = offset[b];
    const float* pcb = pc + (size_t)b * Px * 3;
    const int pbase = w * 1024;              // warp w owns points [w*1024, (w+1)*1024)

    unsigned myflags = 0;                    // bit i = my flag in iteration i
    unsigned mybal   = 0;                    // lane i holds iteration-i ballot
    int cntw = 0;
#pragma unroll 8
    for (int i = 0; i < 32; i++) {
        const int p = pbase + i * 32 + lane;
        bool flag = false;
        if (p < off) {
            const float x = pcb[p * 3 + 0];
            const float y = pcb[p * 3 + 1];
            const float z = pcb[p * 3 + 2];
            flag = (x >= lox) & (x <= hix) &
                   (y >= loy) & (y <= hiy) &
                   (z >= loz) & (z <= hiz);
        }
        const unsigned bal = __ballot_sync(0xffffffffu, flag);
        myflags |= ((unsigned)flag) << i;
        if (lane == i) mybal = bal;
        cntw += __popc(bal);
    }
    if (lane == 0) s_wcnt[w] = cntw;
    __syncthreads();

    int base = 0, tot = 0;
#pragma unroll
    for (int ww = 0; ww < 8; ww++) {
        if (ww < w) base += s_wcnt[ww];
        tot += s_wcnt[ww];
    }

    int* gi = g_idx + bn * Px;
#pragma unroll 8
    for (int i = 0; i < 32; i++) {
        const unsigned bal = __shfl_sync(0xffffffffu, mybal, i);
        if ((myflags >> i) & 1u)
            gi[base + __popc(bal & ((1u << lane) - 1u))] = pbase + i * 32 + lane;
        base += __popc(bal);
    }
    if (t == 0) g_cnt[bn] = tot;
}

// ---------------------------------------------------------------------------
// Kernel B: one CTA per (box, bin). 8 warps = 8 point sub-ranges;
// lane = float4 channel-group (channels 4*lane .. 4*lane+3).
// Index loads are warp-uniform broadcasts, batched x4 for MLP.
// ---------------------------------------------------------------------------
__global__ void __launch_bounds__(256) roipool_max_kernel(
    float* __restrict__ out)               // [B][N][C][8]
{
    __shared__ float s_red[8][128];
    const int k    = blockIdx.x & 7;
    const int bn   = blockIdx.x >> 3;
    const int b    = bn / Nx;
    const int t    = threadIdx.x;
    const int lane = t & 31;
    const int w    = t >> 5;

    const int cnt = g_cnt[bn];
    const int st = (k * cnt) >> 3;                 // floor(k*cnt/8)
    const int en = ((k + 1) * cnt + 7) >> 3;       // ceil((k+1)*cnt/8)
    const int nb = en - st;                        // == 0 iff cnt == 0

    const int* gi = g_idx + bn * Px + st;
    const float4* ftb = (const float4*)(g_featT + (size_t)b * Px * Cx);

    float4 m = make_float4(NEGV, NEGV, NEGV, NEGV);
    for (int j = w; j < nb; j += 32) {             // 8 warps x unroll 4
        const int p0 = __ldg(gi + j);
        const int p1 = (j + 8  < nb) ? __ldg(gi + j + 8)  : p0;
        const int p2 = (j + 16 < nb) ? __ldg(gi + j + 16) : p0;
        const int p3 = (j + 24 < nb) ? __ldg(gi + j + 24) : p0;
        const float4 v0 = __ldg(ftb + (size_t)p0 * 32 + lane);
        const float4 v1 = __ldg(ftb + (size_t)p1 * 32 + lane);
        const float4 v2 = __ldg(ftb + (size_t)p2 * 32 + lane);
        const float4 v3 = __ldg(ftb + (size_t)p3 * 32 + lane);
        m.x = fmaxf(fmaxf(m.x, v0.x), fmaxf(fmaxf(v1.x, v2.x), v3.x));
        m.y = fmaxf(fmaxf(m.y, v0.y), fmaxf(fmaxf(v1.y, v2.y), v3.y));
        m.z = fmaxf(fmaxf(m.z, v0.z), fmaxf(fmaxf(v1.z, v2.z), v3.z));
        m.w = fmaxf(fmaxf(m.w, v0.w), fmaxf(fmaxf(v1.w, v2.w), v3.w));
    }
    *(float4*)&s_red[w][lane * 4] = m;
    __syncthreads();

    // threads 0..127: channel c = t, reduce over 8 warps, write
    if (t < 128) {
        float r = s_red[0][t];
#pragma unroll
        for (int ww = 1; ww < 8; ww++) r = fmaxf(r, s_red[ww][t]);
        out[((size_t)bn * Cx + t) * G3x + k] = (cnt > 0) ? r : 0.0f;
    }
}

// ---------------------------------------------------------------------------
// Harness entry
// ---------------------------------------------------------------------------
extern "C" void kernel_launch(void* const* d_in, const int* in_sizes, int n_in,
                              void* d_out, int out_size)
{
    const float* boxes  = (const float*)d_in[0];   // (B, N, 6)
    const float* feat   = (const float*)d_in[1];   // (B, C, P)
    const int*   offset = (const int*)  d_in[2];   // (B,)
    const float* pc     = (const float*)d_in[3];   // (B, P, 3)
    float*       out    = (float*)d_out;           // (B, N, C, 2, 2, 2)

    roipool_prep_kernel<<<NB + TP_BLOCKS, 256>>>(feat, boxes, offset, pc);
    roipool_max_kernel<<<NB * G3x, 256>>>(out);
}

// round 7
// speedup vs baseline: 2.2138x; 1.1080x over previous
#include <cuda_runtime.h>

#define Bx 2
#define Nx 32
#define Cx 128
#define Px 8192
#define NB 64
#define G3x 8
#define NEGV (-1e30f)

#define GRIDX 512
#define TP_CTAS 448          // CTAs doing transpose; remaining 64 do compaction
#define TILES 2048           // 32x32 transpose tiles

// Scratch (static device globals — allowed)
__device__ float    g_featT[(size_t)Bx * Px * Cx];  // transposed features [b][p][c]
__device__ int      g_idx[NB * Px];                 // compacted inside-point indices
__device__ int      g_cnt[NB];                      // inside count per box
__device__ unsigned g_bar = 0;                      // grid-barrier ticket counter

// ---------------------------------------------------------------------------
// Single fused kernel.
//  Phase 1 (concurrent):
//    blocks [0, TP_CTAS)      : transpose feat [B][C][P] -> g_featT [B][P][C]
//    blocks [TP_CTAS, GRIDX)  : ordered compaction of inside points per box
//  Grid barrier (single wave guaranteed by __launch_bounds__(256,4):
//    148 SMs x 4 CTAs = 592 >= 512 resident).
//  Phase 2: block (bn,k) computes per-channel max of bin k of box bn.
// ---------------------------------------------------------------------------
__global__ void __launch_bounds__(256, 4) roipool_fused_kernel(
    const float* __restrict__ feat,    // [B][C][P]
    const float* __restrict__ boxes,   // [B][N][6]
    const int*   __restrict__ offset,  // [B]
    const float* __restrict__ pc,      // [B][P][3]
    float*       __restrict__ out)     // [B][N][C][8]
{
    __shared__ __align__(16) float s_tile[32][33];
    __shared__ int   s_wcnt[8];
    __shared__ float s_box[6];
    __shared__ __align__(16) float s_red[8][128];   // float4-stored: must be 16B-aligned

    const int t    = threadIdx.x;
    const int lane = t & 31;
    const int w    = t >> 5;

    // ======================= Phase 1 =======================
    if (blockIdx.x < TP_CTAS) {
        // ---- transpose: 4-5 tiles of 32(C) x 32(P), float4 both sides ----
        for (int tile = blockIdx.x; tile < TILES; tile += TP_CTAS) {
            int id = tile;
            const int p0 = (id & 255) * 32; id >>= 8;
            const int c0 = (id & 3) * 32;   id >>= 2;
            const int b  = id;
            {
                const int tx = t & 7, ty = t >> 3;     // tx: float4 along P
                const float4 v = *(const float4*)(feat + (size_t)b * Cx * Px
                                                  + (size_t)(c0 + ty) * Px + p0 + tx * 4);
                s_tile[ty][tx * 4 + 0] = v.x;
                s_tile[ty][tx * 4 + 1] = v.y;
                s_tile[ty][tx * 4 + 2] = v.z;
                s_tile[ty][tx * 4 + 3] = v.w;
            }
            __syncthreads();
            {
                const int cx = t & 7, py = t >> 3;     // cx: float4 along C
                float4 o;
                o.x = s_tile[cx * 4 + 0][py];
                o.y = s_tile[cx * 4 + 1][py];
                o.z = s_tile[cx * 4 + 2][py];
                o.w = s_tile[cx * 4 + 3][py];
                *(float4*)(g_featT + (size_t)b * Px * Cx
                           + (size_t)(p0 + py) * Cx + c0 + cx * 4) = o;
            }
            __syncthreads();
        }
    } else {
        // ---- compaction: ordered, flags in registers, 2 barriers ----
        const int bn = blockIdx.x - TP_CTAS;
        const int b  = bn / Nx;

        if (t < 6) s_box[t] = boxes[bn * 6 + t];
        __syncthreads();

        const float hx = s_box[3] * 0.5f, hy = s_box[4] * 0.5f, hz = s_box[5] * 0.5f;
        const float lox = s_box[0] - hx, hix = s_box[0] + hx;
        const float loy = s_box[1] - hy, hiy = s_box[1] + hy;
        const float loz = s_box[2] - hz, hiz = s_box[2] + hz;

        const int off = offset[b];
        const float* pcb = pc + (size_t)b * Px * 3;
        const int pbase = w * 1024;          // warp w owns points [w*1024, (w+1)*1024)

        unsigned myflags = 0;                // bit i = my flag in iteration i
        unsigned mybal   = 0;                // lane i holds iteration-i ballot
        int cntw = 0;
#pragma unroll 8
        for (int i = 0; i < 32; i++) {
            const int p = pbase + i * 32 + lane;
            bool flag = false;
            if (p < off) {
                const float x = pcb[p * 3 + 0];
                const float y = pcb[p * 3 + 1];
                const float z = pcb[p * 3 + 2];
                flag = (x >= lox) & (x <= hix) &
                       (y >= loy) & (y <= hiy) &
                       (z >= loz) & (z <= hiz);
            }
            const unsigned bal = __ballot_sync(0xffffffffu, flag);
            myflags |= ((unsigned)flag) << i;
            if (lane == i) mybal = bal;
            cntw += __popc(bal);
        }
        if (lane == 0) s_wcnt[w] = cntw;
        __syncthreads();

        int base = 0, tot = 0;
#pragma unroll
        for (int ww = 0; ww < 8; ww++) {
            if (ww < w) base += s_wcnt[ww];
            tot += s_wcnt[ww];
        }

        int* gi = g_idx + bn * Px;
#pragma unroll 8
        for (int i = 0; i < 32; i++) {
            const unsigned bal = __shfl_sync(0xffffffffu, mybal, i);
            if ((myflags >> i) & 1u)
                gi[base + __popc(bal & ((1u << lane) - 1u))] = pbase + i * 32 + lane;
            base += __popc(bal);
        }
        if (t == 0) g_cnt[bn] = tot;
    }

    // ======================= Grid barrier =======================
    // Replay-safe ticket barrier: each launch adds exactly GRIDX arrivals, so
    // ticket a waits for the counter to reach the end of its own launch's block.
    __syncthreads();
    if (t == 0) {
        __threadfence();
        const unsigned a = atomicAdd(&g_bar, 1u);
        const unsigned target = (a / GRIDX + 1u) * GRIDX;
        volatile unsigned* vb = &g_bar;
        while (*vb < target) { }
    }
    __syncthreads();

    // ======================= Phase 2: per-(box,bin) max =======================
    const int k  = blockIdx.x & 7;
    const int bn = blockIdx.x >> 3;
    const int b  = bn / Nx;

    const int cnt = g_cnt[bn];
    const int st = (k * cnt) >> 3;               // floor(k*cnt/8)
    const int en = ((k + 1) * cnt + 7) >> 3;     // ceil((k+1)*cnt/8)
    const int nb = en - st;                      // == 0 iff cnt == 0

    const int* gi2 = g_idx + bn * Px + st;
    const float4* ftb = (const float4*)(g_featT + (size_t)b * Px * Cx);

    float4 m = make_float4(NEGV, NEGV, NEGV, NEGV);
    for (int j = w; j < nb; j += 32) {           // 8 warps x batch-4 for MLP
        const int p0 = __ldg(gi2 + j);
        const int p1 = (j + 8  < nb) ? __ldg(gi2 + j + 8)  : p0;
        const int p2 = (j + 16 < nb) ? __ldg(gi2 + j + 16) : p0;
        const int p3 = (j + 24 < nb) ? __ldg(gi2 + j + 24) : p0;
        const float4 v0 = __ldg(ftb + (size_t)p0 * 32 + lane);
        const float4 v1 = __ldg(ftb + (size_t)p1 * 32 + lane);
        const float4 v2 = __ldg(ftb + (size_t)p2 * 32 + lane);
        const float4 v3 = __ldg(ftb + (size_t)p3 * 32 + lane);
        m.x = fmaxf(fmaxf(m.x, v0.x), fmaxf(fmaxf(v1.x, v2.x), v3.x));
        m.y = fmaxf(fmaxf(m.y, v0.y), fmaxf(fmaxf(v1.y, v2.y), v3.y));
        m.z = fmaxf(fmaxf(m.z, v0.z), fmaxf(fmaxf(v1.z, v2.z), v3.z));
        m.w = fmaxf(fmaxf(m.w, v0.w), fmaxf(fmaxf(v1.w, v2.w), v3.w));
    }
    *(float4*)&s_red[w][lane * 4] = m;
    __syncthreads();

    if (t < 128) {
        float r = s_red[0][t];
#pragma unroll
        for (int ww = 1; ww < 8; ww++) r = fmaxf(r, s_red[ww][t]);
        out[((size_t)bn * Cx + t) * G3x + k] = (cnt > 0) ? r : 0.0f;
    }
}

// ---------------------------------------------------------------------------
// Harness entry — single launch
// ---------------------------------------------------------------------------
extern "C" void kernel_launch(void* const* d_in, const int* in_sizes, int n_in,
                              void* d_out, int out_size)
{
    const float* boxes  = (const float*)d_in[0];   // (B, N, 6)
    const float* feat   = (const float*)d_in[1];   // (B, C, P)
    const int*   offset = (const int*)  d_in[2];   // (B,)
    const float* pc     = (const float*)d_in[3];   // (B, P, 3)
    float*       out    = (float*)d_out;           // (B, N, C, 2, 2, 2)

    roipool_fused_kernel<<<GRIDX, 256>>>(feat, boxes, offset, pc, out);
}

// round 8
// speedup vs baseline: 2.2879x; 1.0335x over previous
#include <cuda_runtime.h>

#define Bx 2
#define Nx 32
#define Cx 128
#define Px 8192
#define NB 64
#define G3x 8
#define NEGV (-1e30f)

#define GRIDX 512
#define TP_CTAS 448          // CTAs doing transpose; remaining 64 do compaction
#define TILES 2048           // 32x32 transpose tiles

// Scratch (static device globals — allowed)
__device__ float    g_featT[(size_t)Bx * Px * Cx];  // transposed features [b][p][c]
__device__ int      g_idx[NB * Px];                 // compacted inside-point indices
__device__ int      g_cnt[NB];                      // inside count per box
__device__ unsigned g_bar = 0;                      // grid-barrier ticket counter

// ---------------------------------------------------------------------------
// Single fused kernel.
//  Phase 1 (concurrent):
//    blocks [0, TP_CTAS)      : transpose feat [B][C][P] -> g_featT [B][P][C]
//                               (tiles with p0 >= offset[b] skipped: never read)
//    blocks [TP_CTAS, GRIDX)  : ordered compaction of inside points per box
//  Grid barrier: ticket counter + exponential-backoff spin (replay-safe).
//  Phase 2: block (bn,k) computes per-channel max of bin k of box bn.
// ---------------------------------------------------------------------------
__global__ void __launch_bounds__(256, 4) roipool_fused_kernel(
    const float* __restrict__ feat,    // [B][C][P]
    const float* __restrict__ boxes,   // [B][N][6]
    const int*   __restrict__ offset,  // [B]
    const float* __restrict__ pc,      // [B][P][3]
    float*       __restrict__ out)     // [B][N][C][8]
{
    __shared__ __align__(16) float s_tile[32][33];
    __shared__ int   s_wcnt[8];
    __shared__ float s_box[6];
    __shared__ __align__(16) float s_red[8][128];   // float4-stored

    const int t    = threadIdx.x;
    const int lane = t & 31;
    const int w    = t >> 5;

    // ======================= Phase 1 =======================
    if (blockIdx.x < TP_CTAS) {
        const int off0 = __ldg(offset + 0);
        const int off1 = __ldg(offset + 1);
        const int tx = t & 7, ty = t >> 3;           // load mapping
        for (int tile = blockIdx.x; tile < TILES; tile += TP_CTAS) {
            int id = tile;
            const int p0 = (id & 255) * 32; id >>= 8;
            const int c0 = (id & 3) * 32;   id >>= 2;
            const int b  = id;
            if (p0 >= (b ? off1 : off0)) continue;   // rows never referenced

            // LDG issued BEFORE the barrier: latency hides behind bar wait
            const float4 v = *(const float4*)(feat + (size_t)b * Cx * Px
                                              + (size_t)(c0 + ty) * Px + p0 + tx * 4);
            __syncthreads();                         // prev iter's readers done
            s_tile[ty][tx * 4 + 0] = v.x;
            s_tile[ty][tx * 4 + 1] = v.y;
            s_tile[ty][tx * 4 + 2] = v.z;
            s_tile[ty][tx * 4 + 3] = v.w;
            __syncthreads();
            {
                const int cx = t & 7, py = t >> 3;   // store mapping
                float4 o;
                o.x = s_tile[cx * 4 + 0][py];
                o.y = s_tile[cx * 4 + 1][py];
                o.z = s_tile[cx * 4 + 2][py];
                o.w = s_tile[cx * 4 + 3][py];
                *(float4*)(g_featT + (size_t)b * Px * Cx
                           + (size_t)(p0 + py) * Cx + c0 + cx * 4) = o;
            }
        }
    } else {
        // ---- compaction: ordered, flags in registers, 2 barriers ----
        const int bn = blockIdx.x - TP_CTAS;
        const int b  = bn / Nx;

        if (t < 6) s_box[t] = boxes[bn * 6 + t];
        __syncthreads();

        const float hx = s_box[3] * 0.5f, hy = s_box[4] * 0.5f, hz = s_box[5] * 0.5f;
        const float lox = s_box[0] - hx, hix = s_box[0] + hx;
        const float loy = s_box[1] - hy, hiy = s_box[1] + hy;
        const float loz = s_box[2] - hz, hiz = s_box[2] + hz;

        const int off = offset[b];
        const float* pcb = pc + (size_t)b * Px * 3;
        const int pbase = w * 1024;          // warp w owns points [w*1024, (w+1)*1024)

        unsigned myflags = 0;                // bit i = my flag in iteration i
        unsigned mybal   = 0;                // lane i holds iteration-i ballot
        int cntw = 0;
#pragma unroll 8
        for (int i = 0; i < 32; i++) {
            const int p = pbase + i * 32 + lane;
            bool flag = false;
            if (p < off) {
                const float x = pcb[p * 3 + 0];
                const float y = pcb[p * 3 + 1];
                const float z = pcb[p * 3 + 2];
                flag = (x >= lox) & (x <= hix) &
                       (y >= loy) & (y <= hiy) &
                       (z >= loz) & (z <= hiz);
            }
            const unsigned bal = __ballot_sync(0xffffffffu, flag);
            myflags |= ((unsigned)flag) << i;
            if (lane == i) mybal = bal;
            cntw += __popc(bal);
        }
        if (lane == 0) s_wcnt[w] = cntw;
        __syncthreads();

        int base = 0, tot = 0;
#pragma unroll
        for (int ww = 0; ww < 8; ww++) {
            if (ww < w) base += s_wcnt[ww];
            tot += s_wcnt[ww];
        }

        int* gi = g_idx + bn * Px;
#pragma unroll 8
        for (int i = 0; i < 32; i++) {
            const unsigned bal = __shfl_sync(0xffffffffu, mybal, i);
            if ((myflags >> i) & 1u)
                gi[base + __popc(bal & ((1u << lane) - 1u))] = pbase + i * 32 + lane;
            base += __popc(bal);
        }
        if (t == 0) g_cnt[bn] = tot;
    }

    // ======================= Grid barrier =======================
    // Replay-safe ticket barrier with exponential backoff: without backoff,
    // 512 CTAs spin-polling one L2 address serialize at the LTS and delay the
    // arrival atomics themselves.
    __syncthreads();
    if (t == 0) {
        __threadfence();
        const unsigned a = atomicAdd(&g_bar, 1u);
        const unsigned target = (a / GRIDX + 1u) * GRIDX;
        volatile unsigned* vb = &g_bar;
        unsigned ns = 64;
        while (*vb < target) {
            __nanosleep(ns);
            if (ns < 1024) ns <<= 1;
        }
    }
    __syncthreads();

    // ======================= Phase 2: per-(box,bin) max =======================
    const int k  = blockIdx.x & 7;
    const int bn = blockIdx.x >> 3;
    const int b  = bn / Nx;

    const int cnt = g_cnt[bn];
    const int st = (k * cnt) >> 3;               // floor(k*cnt/8)
    const int en = ((k + 1) * cnt + 7) >> 3;     // ceil((k+1)*cnt/8)
    const int nb = en - st;                      // == 0 iff cnt == 0

    const int* gi2 = g_idx + bn * Px + st;
    const float4* ftb = (const float4*)(g_featT + (size_t)b * Px * Cx);

    float4 m = make_float4(NEGV, NEGV, NEGV, NEGV);
    for (int j = w; j < nb; j += 32) {           // 8 warps x batch-4 for MLP
        const int p0 = __ldg(gi2 + j);
        const int p1 = (j + 8  < nb) ? __ldg(gi2 + j + 8)  : p0;
        const int p2 = (j + 16 < nb) ? __ldg(gi2 + j + 16) : p0;
        const int p3 = (j + 24 < nb) ? __ldg(gi2 + j + 24) : p0;
        const float4 v0 = __ldg(ftb + (size_t)p0 * 32 + lane);
        const float4 v1 = __ldg(ftb + (size_t)p1 * 32 + lane);
        const float4 v2 = __ldg(ftb + (size_t)p2 * 32 + lane);
        const float4 v3 = __ldg(ftb + (size_t)p3 * 32 + lane);
        m.x = fmaxf(fmaxf(m.x, v0.x), fmaxf(fmaxf(v1.x, v2.x), v3.x));
        m.y = fmaxf(fmaxf(m.y, v0.y), fmaxf(fmaxf(v1.y, v2.y), v3.y));
        m.z = fmaxf(fmaxf(m.z, v0.z), fmaxf(fmaxf(v1.z, v2.z), v3.z));
        m.w = fmaxf(fmaxf(m.w, v0.w), fmaxf(fmaxf(v1.w, v2.w), v3.w));
    }
    *(float4*)&s_red[w][lane * 4] = m;
    __syncthreads();

    if (t < 128) {
        float r = s_red[0][t];
#pragma unroll
        for (int ww = 1; ww < 8; ww++) r = fmaxf(r, s_red[ww][t]);
        out[((size_t)bn * Cx + t) * G3x + k] = (cnt > 0) ? r : 0.0f;
    }
}

// ---------------------------------------------------------------------------
// Harness entry — single launch
// ---------------------------------------------------------------------------
extern "C" void kernel_launch(void* const* d_in, const int* in_sizes, int n_in,
                              void* d_out, int out_size)
{
    const float* boxes  = (const float*)d_in[0];   // (B, N, 6)
    const float* feat   = (const float*)d_in[1];   // (B, C, P)
    const int*   offset = (const int*)  d_in[2];   // (B,)
    const float* pc     = (const float*)d_in[3];   // (B, P, 3)
    float*       out    = (float*)d_out;           // (B, N, C, 2, 2, 2)

    roipool_fused_kernel<<<GRIDX, 256>>>(feat, boxes, offset, pc, out);
}

// round 9
// speedup vs baseline: 2.7703x; 1.2108x over previous
#include <cuda_runtime.h>

#define Bx 2
#define Nx 32
#define Cx 128
#define Px 8192
#define NB 64
#define G3x 8
#define NEGV (-1e30f)
#define GRIDX 512

// Scratch (static device globals — allowed)
__device__ float    g_featT[(size_t)Bx * Px * Cx];  // transposed features [b][p][c]
__device__ int      g_idx[NB * Px];                 // per-box per-segment compacted lists
__device__ int      g_segcnt[NB * 8];               // per-box per-segment counts
__device__ unsigned g_bar = 0;                      // grid-barrier ticket counter

// ---------------------------------------------------------------------------
// One kernel, 512 CTAs, perfectly uniform work per CTA = (box bn, bin k):
//  Pre-barrier: transpose 4 tiles (all loads up front, 1 barrier) +
//               compact segment k (1024 points) of box bn.
//  Grid barrier (ticket + backoff; 4 CTAs/SM x 148 = 592 >= 512 resident).
//  Post-barrier: prefix of 8 segment counts -> bin [st,en), assemble indices
//               into smem, coalesced float4 gather-max over featT.
// ---------------------------------------------------------------------------
__global__ void __launch_bounds__(256, 4) roipool_fused_kernel(
    const float* __restrict__ feat,    // [B][C][P]
    const float* __restrict__ boxes,   // [B][N][6]
    const int*   __restrict__ offset,  // [B]
    const float* __restrict__ pc,      // [B][P][3]
    float*       __restrict__ out)     // [B][N][C][8]
{
    __shared__ __align__(16) float s_tile[4][32][33];
    __shared__ int   s_wcnt[8];
    __shared__ float s_box[6];
    __shared__ int   s_bin[1032];
    __shared__ __align__(16) float s_red[8][128];

    const int g    = blockIdx.x;
    const int t    = threadIdx.x;
    const int lane = t & 31;
    const int w    = t >> 5;
    const int bn   = g >> 3;        // box
    const int k    = g & 7;         // bin == segment
    const int bb   = bn >> 5;       // batch of this box

    const int off0 = __ldg(offset + 0);
    const int off1 = __ldg(offset + 1);

    if (t < 6) s_box[t] = boxes[bn * 6 + t];

    // ---- transpose 4 tiles (ids 4g..4g+3: same b,c0; p0,+32,+64,+96) ----
    const int tile0 = 4 * g;
    const int p0 = (tile0 & 255) * 32;
    const int c0 = ((tile0 >> 8) & 3) * 32;
    const int bt = tile0 >> 10;
    const int offt = bt ? off1 : off0;
    {
        const int tx = t & 7, ty = t >> 3;
        const float* src = feat + (size_t)bt * Cx * Px + (size_t)(c0 + ty) * Px
                           + p0 + tx * 4;
#pragma unroll
        for (int i = 0; i < 4; i++) {
            if (p0 + 32 * i < offt) {                 // rows never referenced -> skip
                const float4 v = *(const float4*)(src + 32 * i);
                s_tile[i][ty][tx * 4 + 0] = v.x;
                s_tile[i][ty][tx * 4 + 1] = v.y;
                s_tile[i][ty][tx * 4 + 2] = v.z;
                s_tile[i][ty][tx * 4 + 3] = v.w;
            }
        }
    }
    __syncthreads();                                  // also publishes s_box
    {
        const int cx = t & 7, py = t >> 3;
        float* dst = g_featT + (size_t)bt * Px * Cx + (size_t)(p0 + py) * Cx
                     + c0 + cx * 4;
#pragma unroll
        for (int i = 0; i < 4; i++) {
            if (p0 + 32 * i < offt) {
                float4 o;
                o.x = s_tile[i][cx * 4 + 0][py];
                o.y = s_tile[i][cx * 4 + 1][py];
                o.z = s_tile[i][cx * 4 + 2][py];
                o.w = s_tile[i][cx * 4 + 3][py];
                *(float4*)(dst + (size_t)(32 * i) * Cx) = o;
            }
        }
    }

    // ---- compact segment k (points [k*1024, (k+1)*1024)) of box bn ----
    const float hx = s_box[3] * 0.5f, hy = s_box[4] * 0.5f, hz = s_box[5] * 0.5f;
    const float lox = s_box[0] - hx, hix = s_box[0] + hx;
    const float loy = s_box[1] - hy, hiy = s_box[1] + hy;
    const float loz = s_box[2] - hz, hiz = s_box[2] + hz;
    const int offb = bb ? off1 : off0;
    const float* pcb = pc + (size_t)bb * Px * 3;
    const int wseg = k * 1024 + w * 128;              // this warp's 128 points

    unsigned bal[4];
    unsigned fl = 0;
    int cntw = 0;
#pragma unroll
    for (int i = 0; i < 4; i++) {
        const int p = wseg + i * 32 + lane;
        bool flag = false;
        if (p < offb) {
            const float x = pcb[p * 3 + 0];
            const float y = pcb[p * 3 + 1];
            const float z = pcb[p * 3 + 2];
            flag = (x >= lox) & (x <= hix) &
                   (y >= loy) & (y <= hiy) &
                   (z >= loz) & (z <= hiz);
        }
        bal[i] = __ballot_sync(0xffffffffu, flag);
        fl |= ((unsigned)flag) << i;
        cntw += __popc(bal[i]);
    }
    if (lane == 0) s_wcnt[w] = cntw;
    __syncthreads();

    int base = 0, tot = 0;
#pragma unroll
    for (int ww = 0; ww < 8; ww++) {
        if (ww < w) base += s_wcnt[ww];
        tot += s_wcnt[ww];
    }
    int* gi = g_idx + bn * Px + k * 1024;             // segment-local list
#pragma unroll
    for (int i = 0; i < 4; i++) {
        if ((fl >> i) & 1u)
            gi[base + __popc(bal[i] & ((1u << lane) - 1u))] = wseg + i * 32 + lane;
        base += __popc(bal[i]);
    }
    if (t == 0) g_segcnt[bn * 8 + k] = tot;

    // ---- grid barrier (replay-safe ticket + exponential backoff) ----
    __syncthreads();
    if (t == 0) {
        __threadfence();
        const unsigned a = atomicAdd(&g_bar, 1u);
        const unsigned target = (a / GRIDX + 1u) * GRIDX;
        volatile unsigned* vb = &g_bar;
        unsigned ns = 32;
        while (*vb < target) { __nanosleep(ns); if (ns < 256) ns <<= 1; }
    }
    __syncthreads();

    // ---- assemble bin k's index list from the 8 segment lists ----
    int c[8];
#pragma unroll
    for (int s = 0; s < 8; s++) c[s] = __ldg(g_segcnt + bn * 8 + s);
    int cnt = 0;
#pragma unroll
    for (int s = 0; s < 8; s++) cnt += c[s];

    const int st = (k * cnt) >> 3;                    // floor(k*cnt/8)
    const int en = ((k + 1) * cnt + 7) >> 3;          // ceil((k+1)*cnt/8)
    const int nb = en - st;                           // == 0 iff cnt == 0

    for (int j = t; j < nb; j += 256) {
        const int r = st + j;                         // global rank in this box
        int acc = 0, seg = 0, loc = 0;
#pragma unroll
        for (int s = 0; s < 8; s++) {
            const int nxt = acc + c[s];
            if (r >= acc && r < nxt) { seg = s; loc = r - acc; }
            acc = nxt;
        }
        s_bin[j] = __ldg(g_idx + bn * Px + seg * 1024 + loc);
    }
    __syncthreads();

    // ---- gather max: 8 warps over points, lane = float4 channel group ----
    const float4* ftb = (const float4*)(g_featT + (size_t)bb * Px * Cx);
    float4 m = make_float4(NEGV, NEGV, NEGV, NEGV);
    for (int j = w; j < nb; j += 32) {                // batch-4 for MLP
        const int q0 = s_bin[j];
        const int q1 = (j + 8  < nb) ? s_bin[j + 8]  : q0;
        const int q2 = (j + 16 < nb) ? s_bin[j + 16] : q0;
        const int q3 = (j + 24 < nb) ? s_bin[j + 24] : q0;
        const float4 v0 = __ldg(ftb + (size_t)q0 * 32 + lane);
        const float4 v1 = __ldg(ftb + (size_t)q1 * 32 + lane);
        const float4 v2 = __ldg(ftb + (size_t)q2 * 32 + lane);
        const float4 v3 = __ldg(ftb + (size_t)q3 * 32 + lane);
        m.x = fmaxf(fmaxf(m.x, v0.x), fmaxf(fmaxf(v1.x, v2.x), v3.x));
        m.y = fmaxf(fmaxf(m.y, v0.y), fmaxf(fmaxf(v1.y, v2.y), v3.y));
        m.z = fmaxf(fmaxf(m.z, v0.z), fmaxf(fmaxf(v1.z, v2.z), v3.z));
        m.w = fmaxf(fmaxf(m.w, v0.w), fmaxf(fmaxf(v1.w, v2.w), v3.w));
    }
    *(float4*)&s_red[w][lane * 4] = m;
    __syncthreads();

    if (t < 128) {
        float r = s_red[0][t];
#pragma unroll
        for (int ww = 1; ww < 8; ww++) r = fmaxf(r, s_red[ww][t]);
        out[((size_t)bn * Cx + t) * G3x + k] = (cnt > 0) ? r : 0.0f;
    }
}

// ---------------------------------------------------------------------------
// Harness entry — single launch
// ---------------------------------------------------------------------------
extern "C" void kernel_launch(void* const* d_in, const int* in_sizes, int n_in,
                              void* d_out, int out_size)
{
    const float* boxes  = (const float*)d_in[0];   // (B, N, 6)
    const float* feat   = (const float*)d_in[1];   // (B, C, P)
    const int*   offset = (const int*)  d_in[2];   // (B,)
    const float* pc     = (const float*)d_in[3];   // (B, P, 3)
    float*       out    = (float*)d_out;           // (B, N, C, 2, 2, 2)

    roipool_fused_kernel<<<GRIDX, 256>>>(feat, boxes, offset, pc, out);
}

// round 11
// speedup vs baseline: 2.9202x; 1.0541x over previous
#include <cuda_runtime.h>

#define Bx 2
#define Nx 32
#define Cx 128
#define Px 8192
#define NB 64
#define G3x 8
#define NEGV (-1e30f)
#define GRIDX 512

// Scratch (static device globals — allowed)
__device__ float    g_featT[(size_t)Bx * Px * Cx];  // transposed features [b][p][c]
__device__ int      g_idx[NB * Px];                 // per-box per-segment compacted lists
__device__ int      g_segcnt[NB * 8];               // per-box per-segment counts
__device__ unsigned g_bar = 0;                      // grid-barrier ticket counter

// ---------------------------------------------------------------------------
// One kernel, 512 CTAs, uniform work per CTA = (box bn, bin k):
//  Pre-barrier (ONE __syncthreads in the work section):
//    - 4 transpose float4 LDGs, p-blocks strided across [0,Px) (balanced skip)
//    - all 12 pc LDGs for segment-k compaction issued alongside (MLP)
//    - STS tiles + warp counts, sync, featT STG + ordered g_idx writes
//  Grid barrier with CORRECT release/acquire fencing:
//    all threads __threadfence() (release) -> sync -> t0 arrival+spin ->
//    t0 __threadfence() (acquire, CCTL.IVALL) -> sync.
//  Post-barrier: prefix of 8 segment counts -> bin [st,en), assemble indices
//    into smem (plain coherent loads), coalesced float4 gather-max.
// ---------------------------------------------------------------------------
__global__ void __launch_bounds__(256, 4) roipool_fused_kernel(
    const float* __restrict__ feat,    // [B][C][P]
    const float* __restrict__ boxes,   // [B][N][6]
    const int*   __restrict__ offset,  // [B]
    const float* __restrict__ pc,      // [B][P][3]
    float*       __restrict__ out)     // [B][N][C][8]
{
    __shared__ __align__(16) float s_tile[4][32][33];
    __shared__ int   s_wcnt[8];
    __shared__ int   s_bin[1032];
    __shared__ __align__(16) float s_red[8][128];

    const int g    = blockIdx.x;
    const int t    = threadIdx.x;
    const int lane = t & 31;
    const int w    = t >> 5;
    const int bn   = g >> 3;        // box
    const int k    = g & 7;         // bin == segment
    const int bb   = bn >> 5;       // batch of this box

    const int off0 = __ldg(offset + 0);
    const int off1 = __ldg(offset + 1);

    // ---- transpose: CTA g owns (b = g>>8, cblock = (g>>6)&3,
    //      p-blocks {(g&63) + 64*i}) -> strided over all 4 quarters ----
    const int bt   = g >> 8;
    const int c0   = ((g >> 6) & 3) * 32;
    const int pidx = g & 63;
    const int offt = bt ? off1 : off0;
    const int tx = t & 7, ty = t >> 3;

    int    pb[4];
    bool   keep[4];
    float4 v[4];
#pragma unroll
    for (int i = 0; i < 4; i++) {
        pb[i]   = (pidx + 64 * i) * 32;
        keep[i] = pb[i] < offt;                      // rows never referenced -> skip
        if (keep[i])
            v[i] = *(const float4*)(feat + (size_t)bt * Cx * Px
                                    + (size_t)(c0 + ty) * Px + pb[i] + tx * 4);
    }

    // ---- box params via uniform __ldg broadcast (kernel inputs: RO-safe) ----
    const float bx0 = __ldg(boxes + bn * 6 + 0);
    const float by0 = __ldg(boxes + bn * 6 + 1);
    const float bz0 = __ldg(boxes + bn * 6 + 2);
    const float hx  = __ldg(boxes + bn * 6 + 3) * 0.5f;
    const float hy  = __ldg(boxes + bn * 6 + 4) * 0.5f;
    const float hz  = __ldg(boxes + bn * 6 + 5) * 0.5f;
    const float lox = bx0 - hx, hix = bx0 + hx;
    const float loy = by0 - hy, hiy = by0 + hy;
    const float loz = bz0 - hz, hiz = bz0 + hz;

    // ---- pc loads for segment k (overlap transpose latency) ----
    const int offb = bb ? off1 : off0;
    const float* pcb = pc + (size_t)bb * Px * 3;
    const int wseg = k * 1024 + w * 128;             // this warp's 128 points

    float qx[4], qy[4], qz[4];
#pragma unroll
    for (int i = 0; i < 4; i++) {
        const int p = wseg + i * 32 + lane;
        if (p < offb) {
            qx[i] = __ldg(pcb + p * 3 + 0);
            qy[i] = __ldg(pcb + p * 3 + 1);
            qz[i] = __ldg(pcb + p * 3 + 2);
        }
    }

    // ---- STS tiles ----
#pragma unroll
    for (int i = 0; i < 4; i++) {
        if (keep[i]) {
            s_tile[i][ty][tx * 4 + 0] = v[i].x;
            s_tile[i][ty][tx * 4 + 1] = v[i].y;
            s_tile[i][ty][tx * 4 + 2] = v[i].z;
            s_tile[i][ty][tx * 4 + 3] = v[i].w;
        }
    }

    // ---- flags + ballots ----
    unsigned bal[4];
    unsigned fl = 0;
    int cntw = 0;
#pragma unroll
    for (int i = 0; i < 4; i++) {
        const int p = wseg + i * 32 + lane;
        bool flag = false;
        if (p < offb)
            flag = (qx[i] >= lox) & (qx[i] <= hix) &
                   (qy[i] >= loy) & (qy[i] <= hiy) &
                   (qz[i] >= loz) & (qz[i] <= hiz);
        bal[i] = __ballot_sync(0xffffffffu, flag);
        fl |= ((unsigned)flag) << i;
        cntw += __popc(bal[i]);
    }
    if (lane == 0) s_wcnt[w] = cntw;

    __syncthreads();                                 // single work-section sync

    // ---- featT stores ----
    {
        const int cx = t & 7, py = t >> 3;
        float* dst = g_featT + (size_t)bt * Px * Cx + (size_t)py * Cx + c0 + cx * 4;
#pragma unroll
        for (int i = 0; i < 4; i++) {
            if (keep[i]) {
                float4 o;
                o.x = s_tile[i][cx * 4 + 0][py];
                o.y = s_tile[i][cx * 4 + 1][py];
                o.z = s_tile[i][cx * 4 + 2][py];
                o.w = s_tile[i][cx * 4 + 3][py];
                *(float4*)(dst + (size_t)pb[i] * Cx) = o;
            }
        }
    }

    // ---- ordered segment-local compaction writes ----
    int base = 0, tot = 0;
#pragma unroll
    for (int ww = 0; ww < 8; ww++) {
        if (ww < w) base += s_wcnt[ww];
        tot += s_wcnt[ww];
    }
    int* gi = g_idx + bn * Px + k * 1024;
#pragma unroll
    for (int i = 0; i < 4; i++) {
        if ((fl >> i) & 1u)
            gi[base + __popc(bal[i] & ((1u << lane) - 1u))] = wseg + i * 32 + lane;
        base += __popc(bal[i]);
    }
    if (t == 0) g_segcnt[bn * 8 + k] = tot;

    // ---- grid barrier: correct release/acquire protocol ----
    __syncthreads();           // all CTA work issued
    __threadfence();           // RELEASE: every thread makes ITS OWN global
                               // writes device-visible (t0's fence alone does
                               // NOT cover other threads' stores)
    __syncthreads();           // all fences complete before arrival
    if (t == 0) {
        const unsigned a = atomicAdd(&g_bar, 1u);
        const unsigned target = (a / GRIDX + 1u) * GRIDX;
        volatile unsigned* vb = &g_bar;
        unsigned ns = 32;
        while (*vb < target) { __nanosleep(ns); if (ns < 256) ns <<= 1; }
        __threadfence();       // ACQUIRE (emits CCTL.IVALL -> clean L1)
    }
    __syncthreads();

    // ---- assemble bin k's index list (plain coherent loads) ----
    int c[8];
#pragma unroll
    for (int s = 0; s < 8; s++) c[s] = g_segcnt[bn * 8 + s];
    int cnt = 0;
#pragma unroll
    for (int s = 0; s < 8; s++) cnt += c[s];

    const int st = (k * cnt) >> 3;                   // floor(k*cnt/8)
    const int en = ((k + 1) * cnt + 7) >> 3;         // ceil((k+1)*cnt/8)
    const int nb = en - st;                          // == 0 iff cnt == 0

    for (int j = t; j < nb; j += 256) {
        const int r = st + j;                        // global rank in this box
        int acc = 0, seg = 0, loc = 0;
#pragma unroll
        for (int s = 0; s < 8; s++) {
            const int nxt = acc + c[s];
            if (r >= acc && r < nxt) { seg = s; loc = r - acc; }
            acc = nxt;
        }
        s_bin[j] = g_idx[bn * Px + seg * 1024 + loc];
    }
    __syncthreads();

    // ---- gather max: 8 warps over points, lane = float4 channel group ----
    const float4* ftb = (const float4*)(g_featT + (size_t)bb * Px * Cx);
    float4 m = make_float4(NEGV, NEGV, NEGV, NEGV);
    for (int j = w; j < nb; j += 32) {               // batch-4 for MLP
        const int q0 = s_bin[j];
        const int q1 = (j + 8  < nb) ? s_bin[j + 8]  : q0;
        const int q2 = (j + 16 < nb) ? s_bin[j + 16] : q0;
        const int q3 = (j + 24 < nb) ? s_bin[j + 24] : q0;
        const float4 v0 = ftb[(size_t)q0 * 32 + lane];
        const float4 v1 = ftb[(size_t)q1 * 32 + lane];
        const float4 v2 = ftb[(size_t)q2 * 32 + lane];
        const float4 v3 = ftb[(size_t)q3 * 32 + lane];
        m.x = fmaxf(fmaxf(m.x, v0.x), fmaxf(fmaxf(v1.x, v2.x), v3.x));
        m.y = fmaxf(fmaxf(m.y, v0.y), fmaxf(fmaxf(v1.y, v2.y), v3.y));
        m.z = fmaxf(fmaxf(m.z, v0.z), fmaxf(fmaxf(v1.z, v2.z), v3.z));
        m.w = fmaxf(fmaxf(m.w, v0.w), fmaxf(fmaxf(v1.w, v2.w), v3.w));
    }
    *(float4*)&s_red[w][lane * 4] = m;
    __syncthreads();

    if (t < 128) {
        float r = s_red[0][t];
#pragma unroll
        for (int ww = 1; ww < 8; ww++) r = fmaxf(r, s_red[ww][t]);
        out[((size_t)bn * Cx + t) * G3x + k] = (cnt > 0) ? r : 0.0f;
    }
}

// ---------------------------------------------------------------------------
// Harness entry — single launch
// ---------------------------------------------------------------------------
extern "C" void kernel_launch(void* const* d_in, const int* in_sizes, int n_in,
                              void* d_out, int out_size)
{
    const float* boxes  = (const float*)d_in[0];   // (B, N, 6)
    const float* feat   = (const float*)d_in[1];   // (B, C, P)
    const int*   offset = (const int*)  d_in[2];   // (B,)
    const float* pc     = (const float*)d_in[3];   // (B, P, 3)
    float*       out    = (float*)d_out;           // (B, N, C, 2, 2, 2)

    roipool_fused_kernel<<<GRIDX, 256>>>(feat, boxes, offset, pc, out);
}